// round 11
// baseline (speedup 1.0000x reference)
#include <cuda_runtime.h>
#include <cuda_fp16.h>
#include <math.h>
#include <stdint.h>

// ---------------------------------------------------------------------------
// Problem constants
#define BB 4
#define SS_ 4096
#define DD 2048
#define HH 1024
#define H2 512
#define EE 8
#define CC 32
#define MM (BB * SS_)   // 16384
#define TAU_F 0.7f

// ---------------------------------------------------------------------------
// Scratch (device globals; no allocations allowed)
__device__ __half g_w1hi[(size_t)HH * DD];   // transposed [N=1024, K=2048]
__device__ __half g_w1lo[(size_t)HH * DD];
__device__ __half g_h1hi[(size_t)MM * HH];
__device__ __half g_w2hi[(size_t)H2 * HH];   // transposed [N=512, K=1024]
__device__ __half g_w2lo[(size_t)H2 * HH];
__device__ float  g_h2sum[(size_t)BB * CC * H2];   // per-chunk column sums of h2
__device__ float  g_cl[BB * CC * EE];
__device__ int    g_sidx[BB * CC];

// ---------------------------------------------------------------------------
__device__ __forceinline__ uint32_t smem_u32(const void* p) {
    uint32_t a;
    asm("{ .reg .u64 t; cvta.to.shared.u64 t, %1; cvt.u32.u64 %0, t; }"
        : "=r"(a) : "l"(p));
    return a;
}
__device__ __forceinline__ void cp16(uint32_t saddr, const void* gaddr) {
    asm volatile("cp.async.cg.shared.global [%0], [%1], 16;" :: "r"(saddr), "l"(gaddr));
}
#define CP_COMMIT() asm volatile("cp.async.commit_group;" ::: "memory")
#define CP_WAIT(n)  asm volatile("cp.async.wait_group %0;" :: "n"(n) : "memory")

__device__ __forceinline__ void ldsm4(uint32_t* r, uint32_t addr) {
    asm volatile("ldmatrix.sync.aligned.m8n8.x4.shared.b16 {%0,%1,%2,%3}, [%4];"
        : "=r"(r[0]), "=r"(r[1]), "=r"(r[2]), "=r"(r[3]) : "r"(addr));
}
// fp32-accumulator HMMA (main hi*hi pass)
__device__ __forceinline__ void mma16816(float* d, const uint32_t* a, const uint32_t* b) {
    asm volatile("mma.sync.aligned.m16n8k16.row.col.f32.f16.f16.f32 "
        "{%0,%1,%2,%3}, {%4,%5,%6,%7}, {%8,%9}, {%0,%1,%2,%3};"
        : "+f"(d[0]), "+f"(d[1]), "+f"(d[2]), "+f"(d[3])
        : "r"(a[0]), "r"(a[1]), "r"(a[2]), "r"(a[3]), "r"(b[0]), "r"(b[1]));
}
// fp16-accumulator HMMA (weight-residual correction pass; terms ~2^-11 of main)
__device__ __forceinline__ void mma16816h(uint32_t* d, const uint32_t* a, const uint32_t* b) {
    asm volatile("mma.sync.aligned.m16n8k16.row.col.f16.f16.f16.f16 "
        "{%0,%1}, {%2,%3,%4,%5}, {%6,%7}, {%0,%1};"
        : "+r"(d[0]), "+r"(d[1])
        : "r"(a[0]), "r"(a[1]), "r"(a[2]), "r"(a[3]), "r"(b[0]), "r"(b[1]));
}

// ---------------------------------------------------------------------------
// Transposing split: in [K, N] fp32 row-major -> out hi/lo [N, K] fp16.
__global__ void transpose_split(const float* __restrict__ in, int K, int N,
                                __half* __restrict__ ohi, __half* __restrict__ olo)
{
    __shared__ float t[32][33];
    int nb = blockIdx.x * 32, kb = blockIdx.y * 32;
    int tx = threadIdx.x, ty = threadIdx.y;  // (32, 8)
#pragma unroll
    for (int i = 0; i < 4; i++) {
        int kr = kb + ty + i * 8;
        t[ty + i * 8][tx] = in[(size_t)kr * N + nb + tx];
    }
    __syncthreads();
#pragma unroll
    for (int i = 0; i < 4; i++) {
        int nr = nb + ty + i * 8;
        float v = t[tx][ty + i * 8];
        __half h = __float2half_rn(v);
        __half l = __float2half_rn(v - __half2float(h));
        ohi[(size_t)nr * K + kb + tx] = h;
        olo[(size_t)nr * K + kb + tx] = l;
    }
}

// ---------------------------------------------------------------------------
// Common tile geometry
#define BM 128
#define BN_ 64
#define BKH 32          // K elements per stage
#define PITCH 40        // halves per fp16 smem row (80 B)
#define A16_BYTES (BM * PITCH * 2)      // 10240
#define B_BYTES (BN_ * PITCH * 2)       // 5120 per B array

// ---------------------------------------------------------------------------
// GEMM1 (fused fp32->fp16 A conversion):
//   h1 = relu(x·w1^T + b1),  x fp32 [M,K] read directly.
// A: cp.async fp32 into 2-slot staging; converted in-kernel to swizzled fp16
// (F2FP on idle pipes; HMMA floor unaffected). B = w1 hi/lo fp16, 3-stage.
// 2 passes: hh (fp32 acc) + hl (fp16 acc).
// ---------------------------------------------------------------------------
#define AF32_PITCHB 144
#define AF32_BYTES (BM * AF32_PITCHB)      // 18432 per slot
#define REL_A16 (2 * AF32_BYTES)           // 36864
#define REL_B (REL_A16 + A16_BYTES)        // 47104
#define G1_SMEM (REL_B + 3 * 2 * B_BYTES)  // 77824 -> 2 CTAs/SM

__global__ __launch_bounds__(256, 2) void gemm1_fused(
    const float* __restrict__ Af,
    const __half* __restrict__ Bhi, const __half* __restrict__ Blo,
    const float* __restrict__ bias, __half* __restrict__ Ohi)
{
    extern __shared__ char smem[];
    const uint32_t sb = smem_u32(smem);
    const int K = DD;                       // 2048
    const int NC = K / BKH;                 // 64
    const int tid = threadIdx.x, wid = tid >> 5, lane = tid & 31;
    const int m0 = blockIdx.y * BM, n0 = blockIdx.x * BN_;
    const int wm = wid & 3, wn = wid >> 2;  // warp grid 4 x 2, tile 32x32

    float acc[2][4][4];
    uint32_t cacc[2][4][2];
#pragma unroll
    for (int i = 0; i < 2; i++)
#pragma unroll
        for (int j = 0; j < 4; j++) {
#pragma unroll
            for (int k = 0; k < 4; k++) acc[i][j][k] = 0.0f;
            cacc[i][j][0] = 0u; cacc[i][j][1] = 0u;
        }

    auto load_stage = [&](int c, int kc) {
        // B fp16, slot c%3
        {
            uint32_t bst = sb + REL_B + (c % 3) * (2 * B_BYTES);
            int row = tid >> 2, seg = tid & 3;
            uint32_t o = row * (PITCH * 2) + seg * 16;
            size_t gb = (size_t)(n0 + row) * K + kc + seg * 8;
            cp16(bst + o,           Bhi + gb);
            cp16(bst + B_BYTES + o, Blo + gb);
        }
        // A fp32 staging, slot c&1: 1024 x 16B segs, 4/thread
        {
            uint32_t ast = sb + (c & 1) * AF32_BYTES;
#pragma unroll
            for (int i = 0; i < 4; i++) {
                int s4 = tid + i * 256;
                int r = s4 >> 3, sg = s4 & 7;
                cp16(ast + r * AF32_PITCHB + sg * 16,
                     Af + (size_t)(m0 + r) * K + kc + sg * 4);
            }
        }
        CP_COMMIT();
    };

    // convert staged fp32 A (slot c&1) -> swizzled fp16 A (single slot)
    auto convert_stage = [&](int c) {
        int row = tid >> 1, half = tid & 1;
        const float* src = reinterpret_cast<const float*>(
            smem + (c & 1) * AF32_BYTES + row * AF32_PITCHB) + half * 16;
        char* dst = smem + REL_A16 + row * (PITCH * 2) + half * 32;
#pragma unroll
        for (int j = 0; j < 2; j++) {
            float4 a = *reinterpret_cast<const float4*>(src + j * 8);
            float4 b = *reinterpret_cast<const float4*>(src + j * 8 + 4);
            __half2 h0 = __floats2half2_rn(a.x, a.y);
            __half2 h1 = __floats2half2_rn(a.z, a.w);
            __half2 h2 = __floats2half2_rn(b.x, b.y);
            __half2 h3 = __floats2half2_rn(b.z, b.w);
            uint4 v;
            v.x = *reinterpret_cast<uint32_t*>(&h0);
            v.y = *reinterpret_cast<uint32_t*>(&h1);
            v.z = *reinterpret_cast<uint32_t*>(&h2);
            v.w = *reinterpret_cast<uint32_t*>(&h3);
            *reinterpret_cast<uint4*>(dst + j * 16) = v;
        }
    };

    const int grp = lane >> 3, lr = lane & 7;
    const int a_row = (grp & 1) * 8 + lr;
    const int a_k   = (grp >> 1) * 8;
    const int b_row = (grp >> 1) * 8 + lr;
    const int b_k   = (grp & 1) * 8;

    uint32_t ah[2][4], bh[2][4], bl[2][4];

    load_stage(0, 0);
    load_stage(1, BKH);

    for (int c = 0; c < NC; c++) {
        if (c == NC - 1) { CP_WAIT(0); } else { CP_WAIT(1); }
        __syncthreads();                       // stage c arrived everywhere
        convert_stage(c);
        __syncthreads();                       // fp16 A ready; staging slot free
        if (c + 2 < NC) load_stage(c + 2, (c + 2) * BKH);

        const uint32_t bst = sb + REL_B + (c % 3) * (2 * B_BYTES);
        const uint32_t a16 = sb + REL_A16;
#pragma unroll
        for (int k16 = 0; k16 < 2; k16++) {
            const int koff = k16 * 16;
#pragma unroll
            for (int mt = 0; mt < 2; mt++) {
                uint32_t ao = (uint32_t)((wm * 32 + mt * 16 + a_row) * (PITCH * 2)
                                         + (koff + a_k) * 2);
                ldsm4(ah[mt], a16 + ao);
            }
#pragma unroll
            for (int np = 0; np < 2; np++) {
                uint32_t bo = (uint32_t)((wn * 32 + np * 16 + b_row) * (PITCH * 2)
                                         + (koff + b_k) * 2);
                ldsm4(bh[np], bst + bo);
                ldsm4(bl[np], bst + B_BYTES + bo);
            }
#pragma unroll
            for (int mt = 0; mt < 2; mt++)
#pragma unroll
                for (int nt = 0; nt < 4; nt++)
                    mma16816(acc[mt][nt], ah[mt], &bh[nt >> 1][(nt & 1) * 2]);
#pragma unroll
            for (int mt = 0; mt < 2; mt++)
#pragma unroll
                for (int nt = 0; nt < 4; nt++)
                    mma16816h(cacc[mt][nt], ah[mt], &bl[nt >> 1][(nt & 1) * 2]);
        }
    }

    // epilogue: hh + correction + bias, relu, fp16 store
    const int cr = lane >> 2, ccol = (lane & 3) * 2;
#pragma unroll
    for (int mt = 0; mt < 2; mt++) {
#pragma unroll
        for (int nt = 0; nt < 4; nt++) {
            float* a4 = acc[mt][nt];
            __half2 c01 = *reinterpret_cast<__half2*>(&cacc[mt][nt][0]);
            __half2 c23 = *reinterpret_cast<__half2*>(&cacc[mt][nt][1]);
            int r0 = m0 + wm * 32 + mt * 16 + cr;
            int col = n0 + wn * 32 + nt * 8 + ccol;
            float bz0 = bias[col], bz1 = bias[col + 1];
            float v00 = fmaxf(a4[0] + __low2float(c01)  + bz0, 0.0f);
            float v01 = fmaxf(a4[1] + __high2float(c01) + bz1, 0.0f);
            float v10 = fmaxf(a4[2] + __low2float(c23)  + bz0, 0.0f);
            float v11 = fmaxf(a4[3] + __high2float(c23) + bz1, 0.0f);
            *reinterpret_cast<__half2*>(Ohi + (size_t)r0 * HH + col) =
                __halves2half2(__float2half_rn(v00), __float2half_rn(v01));
            *reinterpret_cast<__half2*>(Ohi + (size_t)(r0 + 8) * HH + col) =
                __halves2half2(__float2half_rn(v10), __float2half_rn(v11));
        }
    }
}

// ---------------------------------------------------------------------------
// GEMM2 (fused chunk-sum epilogue):
//   h2 = relu(h1·w2^T + b2); this kernel emits per-chunk COLUMN SUMS only
//   (routing is linear: chunk_logits = (sum_t h2 / 128) @ w3 + b3).
// Each CTA = one 128-token chunk x 64 cols -> unique (chunk, col): no atomics.
// ---------------------------------------------------------------------------
#define G2_STAGE (A16_BYTES + 2 * B_BYTES)   // 20480
#define G2_SMEM (3 * G2_STAGE)               // 61440 -> 2 CTAs/SM

__global__ __launch_bounds__(256, 2) void gemm2_chunk(
    const __half* __restrict__ Ahi,
    const __half* __restrict__ Bhi, const __half* __restrict__ Blo,
    const float* __restrict__ bias)
{
    extern __shared__ char smem[];
    const uint32_t sb = smem_u32(smem);
    const int K = HH;                       // 1024
    const int NC = K / BKH;                 // 32
    const int tid = threadIdx.x, wid = tid >> 5, lane = tid & 31;
    const int m0 = blockIdx.y * BM, n0 = blockIdx.x * BN_;
    const int wm = wid & 3, wn = wid >> 2;

    float acc[2][4][4];
    uint32_t cacc[2][4][2];
#pragma unroll
    for (int i = 0; i < 2; i++)
#pragma unroll
        for (int j = 0; j < 4; j++) {
#pragma unroll
            for (int k = 0; k < 4; k++) acc[i][j][k] = 0.0f;
            cacc[i][j][0] = 0u; cacc[i][j][1] = 0u;
        }

    auto load_stage = [&](int s, int kc) {
        uint32_t st = sb + s * G2_STAGE;
#pragma unroll
        for (int i = 0; i < 2; i++) {
            int s4 = tid + i * 256;
            int row = s4 >> 2, seg = s4 & 3;
            cp16(st + row * (PITCH * 2) + seg * 16,
                 Ahi + (size_t)(m0 + row) * K + kc + seg * 8);
        }
        {
            int row = tid >> 2, seg = tid & 3;
            uint32_t o = row * (PITCH * 2) + seg * 16;
            size_t gb = (size_t)(n0 + row) * K + kc + seg * 8;
            cp16(st + A16_BYTES + o,           Bhi + gb);
            cp16(st + A16_BYTES + B_BYTES + o, Blo + gb);
        }
        CP_COMMIT();
    };

    const int grp = lane >> 3, lr = lane & 7;
    const int a_row = (grp & 1) * 8 + lr;
    const int a_k   = (grp >> 1) * 8;
    const int b_row = (grp >> 1) * 8 + lr;
    const int b_k   = (grp & 1) * 8;

    uint32_t ah[2][4], bh[2][4], bl[2][4];

    load_stage(0, 0);
    load_stage(1, BKH);

    for (int c = 0; c < NC; c++) {
        if (c == NC - 1) { CP_WAIT(0); } else { CP_WAIT(1); }
        __syncthreads();
        if (c + 2 < NC) load_stage((c + 2) % 3, (c + 2) * BKH);

        const uint32_t st = sb + (c % 3) * G2_STAGE;
#pragma unroll
        for (int k16 = 0; k16 < 2; k16++) {
            const int koff = k16 * 16;
#pragma unroll
            for (int mt = 0; mt < 2; mt++) {
                uint32_t ao = (uint32_t)((wm * 32 + mt * 16 + a_row) * (PITCH * 2)
                                         + (koff + a_k) * 2);
                ldsm4(ah[mt], st + ao);
            }
#pragma unroll
            for (int np = 0; np < 2; np++) {
                uint32_t bo = (uint32_t)((wn * 32 + np * 16 + b_row) * (PITCH * 2)
                                         + (koff + b_k) * 2);
                ldsm4(bh[np], st + A16_BYTES + bo);
                ldsm4(bl[np], st + A16_BYTES + B_BYTES + bo);
            }
#pragma unroll
            for (int mt = 0; mt < 2; mt++)
#pragma unroll
                for (int nt = 0; nt < 4; nt++)
                    mma16816(acc[mt][nt], ah[mt], &bh[nt >> 1][(nt & 1) * 2]);
#pragma unroll
            for (int mt = 0; mt < 2; mt++)
#pragma unroll
                for (int nt = 0; nt < 4; nt++)
                    mma16816h(cacc[mt][nt], ah[mt], &bl[nt >> 1][(nt & 1) * 2]);
        }
    }

    // epilogue: bias+relu per element, then column sums over the 128 rows
    const int ccol = (lane & 3) * 2;
    float colsum[4][2];
#pragma unroll
    for (int nt = 0; nt < 4; nt++) { colsum[nt][0] = 0.0f; colsum[nt][1] = 0.0f; }
#pragma unroll
    for (int mt = 0; mt < 2; mt++) {
#pragma unroll
        for (int nt = 0; nt < 4; nt++) {
            float* a4 = acc[mt][nt];
            __half2 c01 = *reinterpret_cast<__half2*>(&cacc[mt][nt][0]);
            __half2 c23 = *reinterpret_cast<__half2*>(&cacc[mt][nt][1]);
            int col = n0 + wn * 32 + nt * 8 + ccol;
            float bz0 = bias[col], bz1 = bias[col + 1];
            colsum[nt][0] += fmaxf(a4[0] + __low2float(c01)  + bz0, 0.0f)
                           + fmaxf(a4[2] + __low2float(c23)  + bz0, 0.0f);
            colsum[nt][1] += fmaxf(a4[1] + __high2float(c01) + bz1, 0.0f)
                           + fmaxf(a4[3] + __high2float(c23) + bz1, 0.0f);
        }
    }
    // reduce over cr (lane bits 2..4)
#pragma unroll
    for (int nt = 0; nt < 4; nt++)
#pragma unroll
        for (int j = 0; j < 2; j++)
#pragma unroll
            for (int o = 4; o < 32; o <<= 1)
                colsum[nt][j] += __shfl_xor_sync(0xffffffffu, colsum[nt][j], o);

    __syncthreads();   // pipeline smem no longer read; safe to overlay
    float* sred = reinterpret_cast<float*>(smem);   // [4 (wm)][64 cols]
    if (lane < 4) {
#pragma unroll
        for (int nt = 0; nt < 4; nt++) {
            int cl = wn * 32 + nt * 8 + lane * 2;
            sred[wm * 64 + cl]     = colsum[nt][0];
            sred[wm * 64 + cl + 1] = colsum[nt][1];
        }
    }
    __syncthreads();
    if (tid < 64) {
        float s = sred[tid] + sred[64 + tid] + sred[128 + tid] + sred[192 + tid];
        g_h2sum[(size_t)blockIdx.y * H2 + n0 + tid] = s;
    }
}

// ---------------------------------------------------------------------------
// chunk_logits from per-chunk sums: logits[c][e] = (sum[c]/128)·w3[:,e] + b3[e]
__global__ void chunk_logits_small(const float* __restrict__ w3,
                                   const float* __restrict__ b3)
{
    __shared__ float w3s[H2 * EE];
    __shared__ float red[4][EE];
    const int tid = threadIdx.x;  // 128

    for (int i = tid; i < H2 * EE; i += 128) w3s[i] = w3[i];
    __syncthreads();

    const float* srow = g_h2sum + (size_t)blockIdx.x * H2;
    const int k0 = tid * 4;
    float4 hv = *reinterpret_cast<const float4*>(srow + k0);
    float acc[EE];
#pragma unroll
    for (int e = 0; e < EE; e++) {
        acc[e] = hv.x * w3s[(k0 + 0) * EE + e]
               + hv.y * w3s[(k0 + 1) * EE + e]
               + hv.z * w3s[(k0 + 2) * EE + e]
               + hv.w * w3s[(k0 + 3) * EE + e];
    }
    const int lane = tid & 31, warp = tid >> 5;
#pragma unroll
    for (int e = 0; e < EE; e++) {
        float v = acc[e];
#pragma unroll
        for (int o = 16; o > 0; o >>= 1) v += __shfl_down_sync(0xffffffffu, v, o);
        if (lane == 0) red[warp][e] = v;
    }
    __syncthreads();
    if (tid < EE) {
        float s = red[0][tid] + red[1][tid] + red[2][tid] + red[3][tid];
        g_cl[blockIdx.x * EE + tid] = s * (1.0f / 128.0f) + b3[tid];
    }
}

// ---------------------------------------------------------------------------
// finalize (1 block): hysteresis + stats + small outputs; saves sidx
__global__ void finalize_kernel(float* __restrict__ out)
{
    __shared__ float scl[BB * CC * EE];
    __shared__ int   sidx[BB * CC];
    __shared__ int   sflips[BB];
    __shared__ float sent[BB * CC];
    __shared__ float sutil[EE];
    __shared__ float sscal[3];
    const int tid = threadIdx.x;  // 128

    for (int i = tid; i < BB * CC * EE; i += 128) scl[i] = g_cl[i];
    if (tid < EE) sutil[tid] = 0.0f;
    __syncthreads();

    if (tid < BB) {
        int b = tid, prev = 0, flips = 0;
        for (int c = 0; c < CC; c++) {
            const float* l = &scl[(b * CC + c) * EE];
            int top = 0; float best = l[0];
#pragma unroll
            for (int e = 1; e < EE; e++)
                if (l[e] > best) { best = l[e]; top = e; }
            int fin;
            if (c == 0) fin = top;
            else {
                bool sw = (l[top] - l[prev]) > TAU_F;
                flips += sw ? 1 : 0;
                fin = sw ? top : prev;
            }
            sidx[b * CC + c] = fin;
            prev = fin;
        }
        sflips[tid] = flips;
    }
    __syncthreads();

    {
        const float* l = &scl[tid * EE];
        float mx = l[0];
#pragma unroll
        for (int e = 1; e < EE; e++) mx = fmaxf(mx, l[e]);
        float p[EE], se = 0.0f;
#pragma unroll
        for (int e = 0; e < EE; e++) { p[e] = expf(l[e] - mx); se += p[e]; }
        float ent = 0.0f, inv = 1.0f / se;
#pragma unroll
        for (int e = 0; e < EE; e++) {
            float pr = p[e] * inv;
            ent -= pr * logf(pr + 1e-8f);
        }
        sent[tid] = ent;
        atomicAdd(&sutil[sidx[tid]], 1.0f);
    }
    __syncthreads();

    if (tid == 0) {
        float es = 0.0f;
        for (int i = 0; i < BB * CC; i++) es += sent[i];
        sscal[0] = es / (float)(BB * CC);
        int fl = sflips[0] + sflips[1] + sflips[2] + sflips[3];
        sscal[1] = (float)fl / (float)(BB * (CC - 1));
        float nrm = 0.0f;
        for (int e = 0; e < EE; e++) {
            float u = sutil[e] / (float)(BB * CC);
            nrm += u * u;
        }
        sscal[2] = sqrtf(nrm);
    }
    __syncthreads();

    if (tid < BB * CC) { g_sidx[tid] = sidx[tid]; out[131072 + tid] = (float)sidx[tid]; }
    for (int i = tid; i < BB * CC * EE; i += 128) out[131200 + i] = scl[i];
    if (tid == 0) out[132224] = sscal[0];
    if (tid < EE) out[132225 + tid] = sutil[tid] / (float)(BB * CC);
    if (tid == 0) { out[132233] = sscal[1]; out[132234] = sscal[2]; }
}

// Wide routing_weights writer: one token (8 floats) per thread
__global__ void routing_weights_kernel(float* __restrict__ out)
{
    int t = blockIdx.x * blockDim.x + threadIdx.x;   // 0..16383
    int b = t >> 12;
    int c = (t >> 7) & 31;
    int id = g_sidx[b * CC + c];
    float vv[EE];
#pragma unroll
    for (int e = 0; e < EE; e++) vv[e] = (e == id) ? 1.0f : 0.0f;
    float4 v0 = {vv[0], vv[1], vv[2], vv[3]};
    float4 v1 = {vv[4], vv[5], vv[6], vv[7]};
    *reinterpret_cast<float4*>(out + (size_t)t * EE)     = v0;
    *reinterpret_cast<float4*>(out + (size_t)t * EE + 4) = v1;
}

// ---------------------------------------------------------------------------
extern "C" void kernel_launch(void* const* d_in, const int* in_sizes, int n_in,
                              void* d_out, int out_size)
{
    const float* x  = (const float*)d_in[0];
    // d_in[1] = prev_expert_indices — dead in reference (chunk 0 takes argmax)
    const float* w1 = (const float*)d_in[2];
    const float* b1 = (const float*)d_in[3];
    const float* w2 = (const float*)d_in[4];
    const float* b2 = (const float*)d_in[5];
    const float* w3 = (const float*)d_in[6];
    const float* b3 = (const float*)d_in[7];
    float* out = (float*)d_out;

    cudaFuncSetAttribute(gemm1_fused, cudaFuncAttributeMaxDynamicSharedMemorySize, G1_SMEM);
    cudaFuncSetAttribute(gemm2_chunk, cudaFuncAttributeMaxDynamicSharedMemorySize, G2_SMEM);

    __half *w1hi, *w1lo, *h1hi, *w2hi, *w2lo;
    cudaGetSymbolAddress((void**)&w1hi, g_w1hi);
    cudaGetSymbolAddress((void**)&w1lo, g_w1lo);
    cudaGetSymbolAddress((void**)&h1hi, g_h1hi);
    cudaGetSymbolAddress((void**)&w2hi, g_w2hi);
    cudaGetSymbolAddress((void**)&w2lo, g_w2lo);

    // weight conversions (split hi/lo; residual correction handles weight rounding)
    transpose_split<<<dim3(HH / 32, DD / 32), dim3(32, 8)>>>(w1, DD, HH, w1hi, w1lo);
    transpose_split<<<dim3(H2 / 32, HH / 32), dim3(32, 8)>>>(w2, HH, H2, w2hi, w2lo);

    // GEMM1: x fp32 [16384,2048] -> h1 fp16 [16384,1024] (conversion fused)
    gemm1_fused<<<dim3(HH / BN_, MM / BM), 256, G1_SMEM>>>(
        x, w1hi, w1lo, b1, h1hi);
    // GEMM2: h1 [16384,1024] -> per-chunk column sums of h2 [128,512]
    gemm2_chunk<<<dim3(H2 / BN_, MM / BM), 256, G2_SMEM>>>(
        h1hi, w2hi, w2lo, b2);

    chunk_logits_small<<<BB * CC, 128>>>(w3, b3);
    finalize_kernel<<<1, 128>>>(out);
    routing_weights_kernel<<<MM / 256, 256>>>(out);
}

// round 12
// speedup vs baseline: 1.2390x; 1.2390x over previous
#include <cuda_runtime.h>
#include <cuda_fp16.h>
#include <math.h>
#include <stdint.h>

// ---------------------------------------------------------------------------
// Problem constants
#define BB 4
#define SS_ 4096
#define DD 2048
#define HH 1024
#define H2 512
#define EE 8
#define CC 32
#define MM (BB * SS_)   // 16384
#define TAU_F 0.7f

// ---------------------------------------------------------------------------
// Scratch (device globals; no allocations allowed)
__device__ __half g_xhi[(size_t)MM * DD];
__device__ __half g_w1hi[(size_t)HH * DD];   // transposed [N=1024, K=2048]
__device__ __half g_w1lo[(size_t)HH * DD];
__device__ __half g_h1hi[(size_t)MM * HH];
__device__ __half g_w2hi[(size_t)H2 * HH];   // transposed [N=512, K=1024]
__device__ __half g_w2lo[(size_t)H2 * HH];
__device__ float  g_h2sum[(size_t)BB * CC * H2];   // per-chunk column sums of h2
__device__ float  g_cl[BB * CC * EE];
__device__ int    g_sidx[BB * CC];

// ---------------------------------------------------------------------------
__device__ __forceinline__ uint32_t smem_u32(const void* p) {
    uint32_t a;
    asm("{ .reg .u64 t; cvta.to.shared.u64 t, %1; cvt.u32.u64 %0, t; }"
        : "=r"(a) : "l"(p));
    return a;
}
__device__ __forceinline__ void cp16(uint32_t saddr, const void* gaddr) {
    asm volatile("cp.async.cg.shared.global [%0], [%1], 16;" :: "r"(saddr), "l"(gaddr));
}
#define CP_COMMIT() asm volatile("cp.async.commit_group;" ::: "memory")
#define CP_WAIT(n)  asm volatile("cp.async.wait_group %0;" :: "n"(n) : "memory")

__device__ __forceinline__ void ldsm4(uint32_t* r, uint32_t addr) {
    asm volatile("ldmatrix.sync.aligned.m8n8.x4.shared.b16 {%0,%1,%2,%3}, [%4];"
        : "=r"(r[0]), "=r"(r[1]), "=r"(r[2]), "=r"(r[3]) : "r"(addr));
}
// fp32-accumulator HMMA (main hi*hi pass)
__device__ __forceinline__ void mma16816(float* d, const uint32_t* a, const uint32_t* b) {
    asm volatile("mma.sync.aligned.m16n8k16.row.col.f32.f16.f16.f32 "
        "{%0,%1,%2,%3}, {%4,%5,%6,%7}, {%8,%9}, {%0,%1,%2,%3};"
        : "+f"(d[0]), "+f"(d[1]), "+f"(d[2]), "+f"(d[3])
        : "r"(a[0]), "r"(a[1]), "r"(a[2]), "r"(a[3]), "r"(b[0]), "r"(b[1]));
}
// fp16-accumulator HMMA (weight-residual correction pass; terms ~2^-11 of main)
__device__ __forceinline__ void mma16816h(uint32_t* d, const uint32_t* a, const uint32_t* b) {
    asm volatile("mma.sync.aligned.m16n8k16.row.col.f16.f16.f16.f16 "
        "{%0,%1}, {%2,%3,%4,%5}, {%6,%7}, {%0,%1};"
        : "+r"(d[0]), "+r"(d[1])
        : "r"(a[0]), "r"(a[1]), "r"(a[2]), "r"(a[3]), "r"(b[0]), "r"(b[1]));
}

// ---------------------------------------------------------------------------
// fp32 -> fp16 (hi only) for activations: token-residual error is iid across
// the 128 tokens of a chunk and suppressed by the chunk-mean.
__global__ void convert_hi(const float* __restrict__ in, __half* __restrict__ ohi,
                           size_t n4)
{
    size_t i = (size_t)blockIdx.x * blockDim.x + threadIdx.x;
    size_t stride = (size_t)gridDim.x * blockDim.x;
    for (; i < n4; i += stride) {
        float4 v = reinterpret_cast<const float4*>(in)[i];
        reinterpret_cast<__half2*>(ohi)[i * 2] =
            __halves2half2(__float2half_rn(v.x), __float2half_rn(v.y));
        reinterpret_cast<__half2*>(ohi)[i * 2 + 1] =
            __halves2half2(__float2half_rn(v.z), __float2half_rn(v.w));
    }
}

// Transposing split: in [K, N] fp32 row-major -> out hi/lo [N, K] fp16.
__global__ void transpose_split(const float* __restrict__ in, int K, int N,
                                __half* __restrict__ ohi, __half* __restrict__ olo)
{
    __shared__ float t[32][33];
    int nb = blockIdx.x * 32, kb = blockIdx.y * 32;
    int tx = threadIdx.x, ty = threadIdx.y;  // (32, 8)
#pragma unroll
    for (int i = 0; i < 4; i++) {
        int kr = kb + ty + i * 8;
        t[ty + i * 8][tx] = in[(size_t)kr * N + nb + tx];
    }
    __syncthreads();
#pragma unroll
    for (int i = 0; i < 4; i++) {
        int nr = nb + ty + i * 8;
        float v = t[tx][ty + i * 8];
        __half h = __float2half_rn(v);
        __half l = __float2half_rn(v - __half2float(h));
        ohi[(size_t)nr * K + kb + tx] = h;
        olo[(size_t)nr * K + kb + tx] = l;
    }
}

// ---------------------------------------------------------------------------
// Common tile geometry
#define BM 128
#define BN_ 64
#define BKH 32          // K halves per stage
#define PITCH 40        // halves per smem row (80 B, conflict-friendly)
#define A_BYTES (BM * PITCH * 2)        // 10240
#define B_BYTES (BN_ * PITCH * 2)       // 5120 per B array
#define SB_STAGE (A_BYTES + 2 * B_BYTES)   // 20480: Ahi, Bhi, Blo
#define NSTAGE 3
#define GEMM_SMEM (NSTAGE * SB_STAGE)   // 61440 -> 2 CTAs/SM

// ---------------------------------------------------------------------------
// 2-pass split-fp16 HMMA GEMM:  C[128, 64] per CTA = relu(A·B^T + bias)
// hh (fp32 acc) + hl = Ahi·Blo (fp16 acc, weight-residual correction).
// mode 0: write fp16 hi (h1) to Ohi.
// mode 1: per-chunk column-sum epilogue -> g_h2sum (each CTA = one chunk x
//         64 cols; routing is linear so chunk-mean commutes with GEMM3).
// ---------------------------------------------------------------------------
__global__ __launch_bounds__(256, 2) void gemm_hmma_x2(
    const __half* __restrict__ Ahi,
    const __half* __restrict__ Bhi, const __half* __restrict__ Blo,
    const float* __restrict__ bias, int K, int ldc, int mode,
    __half* __restrict__ Ohi)
{
    extern __shared__ char smem[];
    const uint32_t sb = smem_u32(smem);
    const int tid = threadIdx.x, wid = tid >> 5, lane = tid & 31;
    const int m0 = blockIdx.y * BM, n0 = blockIdx.x * BN_;
    const int wm = wid & 3, wn = wid >> 2;     // warp grid 4 x 2, tile 32x32
    const int NC = K / BKH;

    float acc[2][4][4];                // hh pass, fp32
    uint32_t cacc[2][4][2];            // hl correction, f16x2
#pragma unroll
    for (int i = 0; i < 2; i++)
#pragma unroll
        for (int j = 0; j < 4; j++) {
#pragma unroll
            for (int k = 0; k < 4; k++) acc[i][j][k] = 0.0f;
            cacc[i][j][0] = 0u; cacc[i][j][1] = 0u;
        }

    auto load_stage = [&](int s, int kc) {
        uint32_t st = sb + s * SB_STAGE;
#pragma unroll
        for (int i = 0; i < 2; i++) {
            int s4 = tid + i * 256;
            int row = s4 >> 2, seg = s4 & 3;
            cp16(st + row * (PITCH * 2) + seg * 16,
                 Ahi + (size_t)(m0 + row) * K + kc + seg * 8);
        }
        {
            int row = tid >> 2, seg = tid & 3;
            uint32_t o = row * (PITCH * 2) + seg * 16;
            size_t gb = (size_t)(n0 + row) * K + kc + seg * 8;
            cp16(st + A_BYTES + o,           Bhi + gb);
            cp16(st + A_BYTES + B_BYTES + o, Blo + gb);
        }
        CP_COMMIT();
    };

    const int grp = lane >> 3, lr = lane & 7;
    const int a_row = (grp & 1) * 8 + lr;
    const int a_k   = (grp >> 1) * 8;
    const int b_row = (grp >> 1) * 8 + lr;
    const int b_k   = (grp & 1) * 8;

    uint32_t ah[2][4], bh[2][4], bl[2][4];

    load_stage(0, 0);
    load_stage(1, BKH);

    for (int c = 0; c < NC; c++) {
        if (c == NC - 1) { CP_WAIT(0); } else { CP_WAIT(1); }
        __syncthreads();
        if (c + 2 < NC) load_stage((c + 2) % NSTAGE, (c + 2) * BKH);

        const uint32_t st = sb + (c % NSTAGE) * SB_STAGE;
#pragma unroll
        for (int k16 = 0; k16 < 2; k16++) {
            const int koff = k16 * 16;
#pragma unroll
            for (int mt = 0; mt < 2; mt++) {
                uint32_t ao = (uint32_t)((wm * 32 + mt * 16 + a_row) * (PITCH * 2)
                                         + (koff + a_k) * 2);
                ldsm4(ah[mt], st + ao);
            }
#pragma unroll
            for (int np = 0; np < 2; np++) {
                uint32_t bo = (uint32_t)((wn * 32 + np * 16 + b_row) * (PITCH * 2)
                                         + (koff + b_k) * 2);
                ldsm4(bh[np], st + A_BYTES + bo);
                ldsm4(bl[np], st + A_BYTES + B_BYTES + bo);
            }
            // pass hh (fp32 accum)
#pragma unroll
            for (int mt = 0; mt < 2; mt++)
#pragma unroll
                for (int nt = 0; nt < 4; nt++)
                    mma16816(acc[mt][nt], ah[mt], &bh[nt >> 1][(nt & 1) * 2]);
            // pass hl (fp16 accum): Ahi * Blo
#pragma unroll
            for (int mt = 0; mt < 2; mt++)
#pragma unroll
                for (int nt = 0; nt < 4; nt++)
                    mma16816h(cacc[mt][nt], ah[mt], &bl[nt >> 1][(nt & 1) * 2]);
        }
    }

    const int cr = lane >> 2, ccol = (lane & 3) * 2;
    if (mode == 0) {
        // epilogue: hh + correction + bias, relu, fp16 store
#pragma unroll
        for (int mt = 0; mt < 2; mt++) {
#pragma unroll
            for (int nt = 0; nt < 4; nt++) {
                float* a4 = acc[mt][nt];
                __half2 c01 = *reinterpret_cast<__half2*>(&cacc[mt][nt][0]);
                __half2 c23 = *reinterpret_cast<__half2*>(&cacc[mt][nt][1]);
                int r0 = m0 + wm * 32 + mt * 16 + cr;
                int col = n0 + wn * 32 + nt * 8 + ccol;
                float bz0 = bias[col], bz1 = bias[col + 1];
                float v00 = fmaxf(a4[0] + __low2float(c01)  + bz0, 0.0f);
                float v01 = fmaxf(a4[1] + __high2float(c01) + bz1, 0.0f);
                float v10 = fmaxf(a4[2] + __low2float(c23)  + bz0, 0.0f);
                float v11 = fmaxf(a4[3] + __high2float(c23) + bz1, 0.0f);
                *reinterpret_cast<__half2*>(Ohi + (size_t)r0 * ldc + col) =
                    __halves2half2(__float2half_rn(v00), __float2half_rn(v01));
                *reinterpret_cast<__half2*>(Ohi + (size_t)(r0 + 8) * ldc + col) =
                    __halves2half2(__float2half_rn(v10), __float2half_rn(v11));
            }
        }
    } else {
        // epilogue: bias+relu, then per-chunk column sums over the 128 rows
        float colsum[4][2];
#pragma unroll
        for (int nt = 0; nt < 4; nt++) { colsum[nt][0] = 0.0f; colsum[nt][1] = 0.0f; }
#pragma unroll
        for (int mt = 0; mt < 2; mt++) {
#pragma unroll
            for (int nt = 0; nt < 4; nt++) {
                float* a4 = acc[mt][nt];
                __half2 c01 = *reinterpret_cast<__half2*>(&cacc[mt][nt][0]);
                __half2 c23 = *reinterpret_cast<__half2*>(&cacc[mt][nt][1]);
                int col = n0 + wn * 32 + nt * 8 + ccol;
                float bz0 = bias[col], bz1 = bias[col + 1];
                colsum[nt][0] += fmaxf(a4[0] + __low2float(c01)  + bz0, 0.0f)
                               + fmaxf(a4[2] + __low2float(c23)  + bz0, 0.0f);
                colsum[nt][1] += fmaxf(a4[1] + __high2float(c01) + bz1, 0.0f)
                               + fmaxf(a4[3] + __high2float(c23) + bz1, 0.0f);
            }
        }
        // reduce over row-groups (lane bits 2..4)
#pragma unroll
        for (int nt = 0; nt < 4; nt++)
#pragma unroll
            for (int j = 0; j < 2; j++)
#pragma unroll
                for (int o = 4; o < 32; o <<= 1)
                    colsum[nt][j] += __shfl_xor_sync(0xffffffffu, colsum[nt][j], o);

        __syncthreads();   // pipeline smem no longer read; safe to overlay
        float* sred = reinterpret_cast<float*>(smem);   // [4 (wm)][64 cols]
        if (lane < 4) {
#pragma unroll
            for (int nt = 0; nt < 4; nt++) {
                int cl = wn * 32 + nt * 8 + lane * 2;
                sred[wm * 64 + cl]     = colsum[nt][0];
                sred[wm * 64 + cl + 1] = colsum[nt][1];
            }
        }
        __syncthreads();
        if (tid < 64) {
            float s = sred[tid] + sred[64 + tid] + sred[128 + tid] + sred[192 + tid];
            g_h2sum[(size_t)blockIdx.y * H2 + n0 + tid] = s;
        }
    }
}

// ---------------------------------------------------------------------------
// chunk_logits from per-chunk sums: logits[c][e] = (sum[c]/128)·w3[:,e] + b3[e]
__global__ void chunk_logits_small(const float* __restrict__ w3,
                                   const float* __restrict__ b3)
{
    __shared__ float w3s[H2 * EE];
    __shared__ float red[4][EE];
    const int tid = threadIdx.x;  // 128

    for (int i = tid; i < H2 * EE; i += 128) w3s[i] = w3[i];
    __syncthreads();

    const float* srow = g_h2sum + (size_t)blockIdx.x * H2;
    const int k0 = tid * 4;
    float4 hv = *reinterpret_cast<const float4*>(srow + k0);
    float acc[EE];
#pragma unroll
    for (int e = 0; e < EE; e++) {
        acc[e] = hv.x * w3s[(k0 + 0) * EE + e]
               + hv.y * w3s[(k0 + 1) * EE + e]
               + hv.z * w3s[(k0 + 2) * EE + e]
               + hv.w * w3s[(k0 + 3) * EE + e];
    }
    const int lane = tid & 31, warp = tid >> 5;
#pragma unroll
    for (int e = 0; e < EE; e++) {
        float v = acc[e];
#pragma unroll
        for (int o = 16; o > 0; o >>= 1) v += __shfl_down_sync(0xffffffffu, v, o);
        if (lane == 0) red[warp][e] = v;
    }
    __syncthreads();
    if (tid < EE) {
        float s = red[0][tid] + red[1][tid] + red[2][tid] + red[3][tid];
        g_cl[blockIdx.x * EE + tid] = s * (1.0f / 128.0f) + b3[tid];
    }
}

// ---------------------------------------------------------------------------
// finalize (1 block): hysteresis + stats + small outputs; saves sidx
__global__ void finalize_kernel(float* __restrict__ out)
{
    __shared__ float scl[BB * CC * EE];
    __shared__ int   sidx[BB * CC];
    __shared__ int   sflips[BB];
    __shared__ float sent[BB * CC];
    __shared__ float sutil[EE];
    __shared__ float sscal[3];
    const int tid = threadIdx.x;  // 128

    for (int i = tid; i < BB * CC * EE; i += 128) scl[i] = g_cl[i];
    if (tid < EE) sutil[tid] = 0.0f;
    __syncthreads();

    if (tid < BB) {
        int b = tid, prev = 0, flips = 0;
        for (int c = 0; c < CC; c++) {
            const float* l = &scl[(b * CC + c) * EE];
            int top = 0; float best = l[0];
#pragma unroll
            for (int e = 1; e < EE; e++)
                if (l[e] > best) { best = l[e]; top = e; }
            int fin;
            if (c == 0) fin = top;
            else {
                bool sw = (l[top] - l[prev]) > TAU_F;
                flips += sw ? 1 : 0;
                fin = sw ? top : prev;
            }
            sidx[b * CC + c] = fin;
            prev = fin;
        }
        sflips[tid] = flips;
    }
    __syncthreads();

    {
        const float* l = &scl[tid * EE];
        float mx = l[0];
#pragma unroll
        for (int e = 1; e < EE; e++) mx = fmaxf(mx, l[e]);
        float p[EE], se = 0.0f;
#pragma unroll
        for (int e = 0; e < EE; e++) { p[e] = expf(l[e] - mx); se += p[e]; }
        float ent = 0.0f, inv = 1.0f / se;
#pragma unroll
        for (int e = 0; e < EE; e++) {
            float pr = p[e] * inv;
            ent -= pr * logf(pr + 1e-8f);
        }
        sent[tid] = ent;
        atomicAdd(&sutil[sidx[tid]], 1.0f);
    }
    __syncthreads();

    if (tid == 0) {
        float es = 0.0f;
        for (int i = 0; i < BB * CC; i++) es += sent[i];
        sscal[0] = es / (float)(BB * CC);
        int fl = sflips[0] + sflips[1] + sflips[2] + sflips[3];
        sscal[1] = (float)fl / (float)(BB * (CC - 1));
        float nrm = 0.0f;
        for (int e = 0; e < EE; e++) {
            float u = sutil[e] / (float)(BB * CC);
            nrm += u * u;
        }
        sscal[2] = sqrtf(nrm);
    }
    __syncthreads();

    if (tid < BB * CC) { g_sidx[tid] = sidx[tid]; out[131072 + tid] = (float)sidx[tid]; }
    for (int i = tid; i < BB * CC * EE; i += 128) out[131200 + i] = scl[i];
    if (tid == 0) out[132224] = sscal[0];
    if (tid < EE) out[132225 + tid] = sutil[tid] / (float)(BB * CC);
    if (tid == 0) { out[132233] = sscal[1]; out[132234] = sscal[2]; }
}

// Wide routing_weights writer: one token (8 floats) per thread
__global__ void routing_weights_kernel(float* __restrict__ out)
{
    int t = blockIdx.x * blockDim.x + threadIdx.x;   // 0..16383
    int b = t >> 12;
    int c = (t >> 7) & 31;
    int id = g_sidx[b * CC + c];
    float vv[EE];
#pragma unroll
    for (int e = 0; e < EE; e++) vv[e] = (e == id) ? 1.0f : 0.0f;
    float4 v0 = {vv[0], vv[1], vv[2], vv[3]};
    float4 v1 = {vv[4], vv[5], vv[6], vv[7]};
    *reinterpret_cast<float4*>(out + (size_t)t * EE)     = v0;
    *reinterpret_cast<float4*>(out + (size_t)t * EE + 4) = v1;
}

// ---------------------------------------------------------------------------
extern "C" void kernel_launch(void* const* d_in, const int* in_sizes, int n_in,
                              void* d_out, int out_size)
{
    const float* x  = (const float*)d_in[0];
    // d_in[1] = prev_expert_indices — dead in reference (chunk 0 takes argmax)
    const float* w1 = (const float*)d_in[2];
    const float* b1 = (const float*)d_in[3];
    const float* w2 = (const float*)d_in[4];
    const float* b2 = (const float*)d_in[5];
    const float* w3 = (const float*)d_in[6];
    const float* b3 = (const float*)d_in[7];
    float* out = (float*)d_out;

    cudaFuncSetAttribute(gemm_hmma_x2, cudaFuncAttributeMaxDynamicSharedMemorySize, GEMM_SMEM);

    __half *xhi, *w1hi, *w1lo, *h1hi, *w2hi, *w2lo;
    cudaGetSymbolAddress((void**)&xhi, g_xhi);
    cudaGetSymbolAddress((void**)&w1hi, g_w1hi);
    cudaGetSymbolAddress((void**)&w1lo, g_w1lo);
    cudaGetSymbolAddress((void**)&h1hi, g_h1hi);
    cudaGetSymbolAddress((void**)&w2hi, g_w2hi);
    cudaGetSymbolAddress((void**)&w2lo, g_w2lo);

    // input conversions
    convert_hi<<<2048, 256>>>(x, xhi, (size_t)MM * DD / 4);
    transpose_split<<<dim3(HH / 32, DD / 32), dim3(32, 8)>>>(w1, DD, HH, w1hi, w1lo);
    transpose_split<<<dim3(H2 / 32, HH / 32), dim3(32, 8)>>>(w2, HH, H2, w2hi, w2lo);

    // GEMM1: [16384,2048] x [2048->1024] -> h1 (fp16)
    gemm_hmma_x2<<<dim3(HH / BN_, MM / BM), 256, GEMM_SMEM>>>(
        xhi, w1hi, w1lo, b1, DD, HH, 0, h1hi);
    // GEMM2: [16384,1024] x [1024->512] -> per-chunk column sums (fused epilogue)
    gemm_hmma_x2<<<dim3(H2 / BN_, MM / BM), 256, GEMM_SMEM>>>(
        h1hi, w2hi, w2lo, b2, HH, H2, 1, nullptr);

    chunk_logits_small<<<BB * CC, 128>>>(w3, b3);
    finalize_kernel<<<1, 128>>>(out);
    routing_weights_kernel<<<MM / 256, 256>>>(out);
}

// round 15
// speedup vs baseline: 1.4770x; 1.1921x over previous
#include <cuda_runtime.h>
#include <cuda_fp16.h>
#include <math.h>
#include <stdint.h>

// ---------------------------------------------------------------------------
// Problem constants
#define BB 4
#define SS_ 4096
#define DD 2048
#define HH 1024
#define H2 512
#define EE 8
#define CC 32
#define MM (BB * SS_)   // 16384
#define TAU_F 0.7f

// ---------------------------------------------------------------------------
// Scratch (device globals; no allocations allowed)
__device__ __half g_w1hi[(size_t)HH * DD];   // transposed [N=1024, K=2048]
__device__ __half g_h1hi[(size_t)MM * HH];
__device__ __half g_w2hi[(size_t)H2 * HH];   // transposed [N=512, K=1024]
__device__ __half g_w2lo[(size_t)H2 * HH];
__device__ float  g_h2sum[(size_t)BB * CC * H2];   // per-chunk column sums of h2
__device__ float  g_cl[BB * CC * EE];
__device__ int    g_sidx[BB * CC];

// ---------------------------------------------------------------------------
__device__ __forceinline__ uint32_t smem_u32(const void* p) {
    uint32_t a;
    asm("{ .reg .u64 t; cvta.to.shared.u64 t, %1; cvt.u32.u64 %0, t; }"
        : "=r"(a) : "l"(p));
    return a;
}
__device__ __forceinline__ void cp16(uint32_t saddr, const void* gaddr) {
    asm volatile("cp.async.cg.shared.global [%0], [%1], 16;" :: "r"(saddr), "l"(gaddr));
}
#define CP_COMMIT() asm volatile("cp.async.commit_group;" ::: "memory")
#define CP_WAIT(n)  asm volatile("cp.async.wait_group %0;" :: "n"(n) : "memory")

__device__ __forceinline__ void ldsm4(uint32_t* r, uint32_t addr) {
    asm volatile("ldmatrix.sync.aligned.m8n8.x4.shared.b16 {%0,%1,%2,%3}, [%4];"
        : "=r"(r[0]), "=r"(r[1]), "=r"(r[2]), "=r"(r[3]) : "r"(addr));
}
// fp32-accumulator HMMA
__device__ __forceinline__ void mma16816(float* d, const uint32_t* a, const uint32_t* b) {
    asm volatile("mma.sync.aligned.m16n8k16.row.col.f32.f16.f16.f32 "
        "{%0,%1,%2,%3}, {%4,%5,%6,%7}, {%8,%9}, {%0,%1,%2,%3};"
        : "+f"(d[0]), "+f"(d[1]), "+f"(d[2]), "+f"(d[3])
        : "r"(a[0]), "r"(a[1]), "r"(a[2]), "r"(a[3]), "r"(b[0]), "r"(b[1]));
}
// fp16-accumulator HMMA (weight-residual correction; terms ~2^-11 of main)
__device__ __forceinline__ void mma16816h(uint32_t* d, const uint32_t* a, const uint32_t* b) {
    asm volatile("mma.sync.aligned.m16n8k16.row.col.f16.f16.f16.f16 "
        "{%0,%1}, {%2,%3,%4,%5}, {%6,%7}, {%0,%1};"
        : "+r"(d[0]), "+r"(d[1])
        : "r"(a[0]), "r"(a[1]), "r"(a[2]), "r"(a[3]), "r"(b[0]), "r"(b[1]));
}
__device__ __forceinline__ uint32_t pack_h2(float x, float y) {
    __half2 h = __floats2half2_rn(x, y);
    return *reinterpret_cast<uint32_t*>(&h);
}

// ---------------------------------------------------------------------------
// Transpose hi-only: in [K, N] fp32 -> out [N, K] fp16 (for w1; residual
// error is token-weighted and suppressed by the chunk-mean).
__global__ void transpose_hi(const float* __restrict__ in, int K, int N,
                             __half* __restrict__ ohi)
{
    __shared__ float t[32][33];
    int nb = blockIdx.x * 32, kb = blockIdx.y * 32;
    int tx = threadIdx.x, ty = threadIdx.y;  // (32, 8)
#pragma unroll
    for (int i = 0; i < 4; i++) {
        int kr = kb + ty + i * 8;
        t[ty + i * 8][tx] = in[(size_t)kr * N + nb + tx];
    }
    __syncthreads();
#pragma unroll
    for (int i = 0; i < 4; i++) {
        int nr = nb + ty + i * 8;
        ohi[(size_t)nr * K + kb + tx] = __float2half_rn(t[tx][ty + i * 8]);
    }
}

// Transposing split (w2 keeps its correction pass): hi + lo fp16.
__global__ void transpose_split(const float* __restrict__ in, int K, int N,
                                __half* __restrict__ ohi, __half* __restrict__ olo)
{
    __shared__ float t[32][33];
    int nb = blockIdx.x * 32, kb = blockIdx.y * 32;
    int tx = threadIdx.x, ty = threadIdx.y;  // (32, 8)
#pragma unroll
    for (int i = 0; i < 4; i++) {
        int kr = kb + ty + i * 8;
        t[ty + i * 8][tx] = in[(size_t)kr * N + nb + tx];
    }
    __syncthreads();
#pragma unroll
    for (int i = 0; i < 4; i++) {
        int nr = nb + ty + i * 8;
        float v = t[tx][ty + i * 8];
        __half h = __float2half_rn(v);
        __half l = __float2half_rn(v - __half2float(h));
        ohi[(size_t)nr * K + kb + tx] = h;
        olo[(size_t)nr * K + kb + tx] = l;
    }
}

// ---------------------------------------------------------------------------
// Common tile geometry
#define BM 128
#define BN_ 64
#define BKH 32          // K elements per stage
#define PITCH 40        // halves per fp16 smem row (80 B)
#define A16_BYTES (BM * PITCH * 2)      // 10240
#define B_BYTES (BN_ * PITCH * 2)       // 5120 per B array

// ---------------------------------------------------------------------------
// GEMM1 single-pass, fp32 A staged directly:
//   h1 = relu(x·w1hi^T + b1)
// A: fp32 in smem (pitch 40 floats -> conflict-free LDS.64 per half-warp),
// converted to fp16 fragments IN REGISTERS (no extra barriers, unlike the
// failed shared-staging fusion). B: w1hi fp16 via ldmatrix. 3-stage cp.async.
// ---------------------------------------------------------------------------
#define AF_PITCH 40                        // floats per A smem row
#define AF_BYTES (BM * AF_PITCH * 4)       // 20480
#define G1_STAGE (AF_BYTES + B_BYTES)      // 25600
#define G1_SMEM (3 * G1_STAGE)             // 76800 -> 2 CTAs/SM

__global__ __launch_bounds__(256, 2) void gemm1_f32a(
    const float* __restrict__ Af, const __half* __restrict__ Bhi,
    const float* __restrict__ bias, __half* __restrict__ Ohi)
{
    extern __shared__ char smem[];
    const uint32_t sb = smem_u32(smem);
    const int K = DD, NC = K / BKH;        // 2048, 64
    const int tid = threadIdx.x, wid = tid >> 5, lane = tid & 31;
    const int m0 = blockIdx.y * BM, n0 = blockIdx.x * BN_;
    const int wm = wid & 3, wn = wid >> 2; // warp grid 4 x 2, tile 32x32

    float acc[2][4][4];
#pragma unroll
    for (int i = 0; i < 2; i++)
#pragma unroll
        for (int j = 0; j < 4; j++)
#pragma unroll
            for (int k = 0; k < 4; k++) acc[i][j][k] = 0.0f;

    auto load_stage = [&](int s, int kc) {
        uint32_t st = sb + s * G1_STAGE;
        // A fp32: 128 rows x 8 x 16B segments, 4/thread
#pragma unroll
        for (int i = 0; i < 4; i++) {
            int s4 = tid + i * 256;
            int r = s4 >> 3, sg = s4 & 7;
            cp16(st + r * (AF_PITCH * 4) + sg * 16,
                 Af + (size_t)(m0 + r) * K + kc + sg * 4);
        }
        // B fp16: 64 rows x 4 x 16B, 1/thread
        {
            int row = tid >> 2, seg = tid & 3;
            cp16(st + AF_BYTES + row * (PITCH * 2) + seg * 16,
                 Bhi + (size_t)(n0 + row) * K + kc + seg * 8);
        }
        CP_COMMIT();
    };

    // B ldmatrix lane addressing
    const int grp = lane >> 3, lr = lane & 7;
    const int b_row = (grp >> 1) * 8 + lr;
    const int b_k   = (grp & 1) * 8;
    // A LDS.64 lane addressing (mma m16n8k16 A layout)
    const int fr = lane >> 2;          // row 0..7
    const int fk = (lane & 3) * 2;     // k 0,2,4,6

    uint32_t ah[2][4], bh[2][4];

    load_stage(0, 0);
    load_stage(1, BKH);

    for (int c = 0; c < NC; c++) {
        if (c == NC - 1) { CP_WAIT(0); } else { CP_WAIT(1); }
        __syncthreads();
        if (c + 2 < NC) load_stage((c + 2) % 3, (c + 2) * BKH);

        const int s = c % 3;
        const float* stA = reinterpret_cast<const float*>(smem + s * G1_STAGE);
        const uint32_t stB = sb + s * G1_STAGE + AF_BYTES;
#pragma unroll
        for (int k16 = 0; k16 < 2; k16++) {
            const int koff = k16 * 16;
            // A fragments: LDS.64 fp32 + register cvt to fp16x2
#pragma unroll
            for (int mt = 0; mt < 2; mt++) {
                const float* ap = stA + (wm * 32 + mt * 16 + fr) * AF_PITCH
                                      + koff + fk;
                float2 f0 = *reinterpret_cast<const float2*>(ap);
                float2 f1 = *reinterpret_cast<const float2*>(ap + 8 * AF_PITCH);
                float2 f2 = *reinterpret_cast<const float2*>(ap + 8);
                float2 f3 = *reinterpret_cast<const float2*>(ap + 8 * AF_PITCH + 8);
                ah[mt][0] = pack_h2(f0.x, f0.y);
                ah[mt][1] = pack_h2(f1.x, f1.y);
                ah[mt][2] = pack_h2(f2.x, f2.y);
                ah[mt][3] = pack_h2(f3.x, f3.y);
            }
#pragma unroll
            for (int np = 0; np < 2; np++) {
                uint32_t bo = (uint32_t)((wn * 32 + np * 16 + b_row) * (PITCH * 2)
                                         + (koff + b_k) * 2);
                ldsm4(bh[np], stB + bo);
            }
#pragma unroll
            for (int mt = 0; mt < 2; mt++)
#pragma unroll
                for (int nt = 0; nt < 4; nt++)
                    mma16816(acc[mt][nt], ah[mt], &bh[nt >> 1][(nt & 1) * 2]);
        }
    }

    // epilogue: bias + relu, fp16 store
    const int cr = lane >> 2, ccol = (lane & 3) * 2;
#pragma unroll
    for (int mt = 0; mt < 2; mt++) {
#pragma unroll
        for (int nt = 0; nt < 4; nt++) {
            float* a4 = acc[mt][nt];
            int r0 = m0 + wm * 32 + mt * 16 + cr;
            int col = n0 + wn * 32 + nt * 8 + ccol;
            float bz0 = bias[col], bz1 = bias[col + 1];
            float v00 = fmaxf(a4[0] + bz0, 0.0f);
            float v01 = fmaxf(a4[1] + bz1, 0.0f);
            float v10 = fmaxf(a4[2] + bz0, 0.0f);
            float v11 = fmaxf(a4[3] + bz1, 0.0f);
            *reinterpret_cast<__half2*>(Ohi + (size_t)r0 * HH + col) =
                __halves2half2(__float2half_rn(v00), __float2half_rn(v01));
            *reinterpret_cast<__half2*>(Ohi + (size_t)(r0 + 8) * HH + col) =
                __halves2half2(__float2half_rn(v10), __float2half_rn(v11));
        }
    }
}

// ---------------------------------------------------------------------------
// GEMM2: 2-pass (hh fp32 + hl fp16 correction), fused per-chunk column-sum
// epilogue -> g_h2sum. Each CTA = one 128-token chunk x 64 cols.
// ---------------------------------------------------------------------------
#define SB_STAGE (A16_BYTES + 2 * B_BYTES)   // 20480
#define G2_SMEM (3 * SB_STAGE)               // 61440 -> 2 CTAs/SM

__global__ __launch_bounds__(256, 2) void gemm2_chunk(
    const __half* __restrict__ Ahi,
    const __half* __restrict__ Bhi, const __half* __restrict__ Blo,
    const float* __restrict__ bias)
{
    extern __shared__ char smem[];
    const uint32_t sb = smem_u32(smem);
    const int K = HH, NC = K / BKH;        // 1024, 32
    const int tid = threadIdx.x, wid = tid >> 5, lane = tid & 31;
    const int m0 = blockIdx.y * BM, n0 = blockIdx.x * BN_;
    const int wm = wid & 3, wn = wid >> 2;

    float acc[2][4][4];
    uint32_t cacc[2][4][2];
#pragma unroll
    for (int i = 0; i < 2; i++)
#pragma unroll
        for (int j = 0; j < 4; j++) {
#pragma unroll
            for (int k = 0; k < 4; k++) acc[i][j][k] = 0.0f;
            cacc[i][j][0] = 0u; cacc[i][j][1] = 0u;
        }

    auto load_stage = [&](int s, int kc) {
        uint32_t st = sb + s * SB_STAGE;
#pragma unroll
        for (int i = 0; i < 2; i++) {
            int s4 = tid + i * 256;
            int row = s4 >> 2, seg = s4 & 3;
            cp16(st + row * (PITCH * 2) + seg * 16,
                 Ahi + (size_t)(m0 + row) * K + kc + seg * 8);
        }
        {
            int row = tid >> 2, seg = tid & 3;
            uint32_t o = row * (PITCH * 2) + seg * 16;
            size_t gb = (size_t)(n0 + row) * K + kc + seg * 8;
            cp16(st + A16_BYTES + o,           Bhi + gb);
            cp16(st + A16_BYTES + B_BYTES + o, Blo + gb);
        }
        CP_COMMIT();
    };

    const int grp = lane >> 3, lr = lane & 7;
    const int a_row = (grp & 1) * 8 + lr;
    const int a_k   = (grp >> 1) * 8;
    const int b_row = (grp >> 1) * 8 + lr;
    const int b_k   = (grp & 1) * 8;

    uint32_t ah[2][4], bh[2][4], bl[2][4];

    load_stage(0, 0);
    load_stage(1, BKH);

    for (int c = 0; c < NC; c++) {
        if (c == NC - 1) { CP_WAIT(0); } else { CP_WAIT(1); }
        __syncthreads();
        if (c + 2 < NC) load_stage((c + 2) % 3, (c + 2) * BKH);

        const uint32_t st = sb + (c % 3) * SB_STAGE;
#pragma unroll
        for (int k16 = 0; k16 < 2; k16++) {
            const int koff = k16 * 16;
#pragma unroll
            for (int mt = 0; mt < 2; mt++) {
                uint32_t ao = (uint32_t)((wm * 32 + mt * 16 + a_row) * (PITCH * 2)
                                         + (koff + a_k) * 2);
                ldsm4(ah[mt], st + ao);
            }
#pragma unroll
            for (int np = 0; np < 2; np++) {
                uint32_t bo = (uint32_t)((wn * 32 + np * 16 + b_row) * (PITCH * 2)
                                         + (koff + b_k) * 2);
                ldsm4(bh[np], st + A16_BYTES + bo);
                ldsm4(bl[np], st + A16_BYTES + B_BYTES + bo);
            }
#pragma unroll
            for (int mt = 0; mt < 2; mt++)
#pragma unroll
                for (int nt = 0; nt < 4; nt++)
                    mma16816(acc[mt][nt], ah[mt], &bh[nt >> 1][(nt & 1) * 2]);
#pragma unroll
            for (int mt = 0; mt < 2; mt++)
#pragma unroll
                for (int nt = 0; nt < 4; nt++)
                    mma16816h(cacc[mt][nt], ah[mt], &bl[nt >> 1][(nt & 1) * 2]);
        }
    }

    // epilogue: bias+relu, then per-chunk column sums over the 128 rows
    const int ccol = (lane & 3) * 2;
    float colsum[4][2];
#pragma unroll
    for (int nt = 0; nt < 4; nt++) { colsum[nt][0] = 0.0f; colsum[nt][1] = 0.0f; }
#pragma unroll
    for (int mt = 0; mt < 2; mt++) {
#pragma unroll
        for (int nt = 0; nt < 4; nt++) {
            float* a4 = acc[mt][nt];
            __half2 c01 = *reinterpret_cast<__half2*>(&cacc[mt][nt][0]);
            __half2 c23 = *reinterpret_cast<__half2*>(&cacc[mt][nt][1]);
            int col = n0 + wn * 32 + nt * 8 + ccol;
            float bz0 = bias[col], bz1 = bias[col + 1];
            colsum[nt][0] += fmaxf(a4[0] + __low2float(c01)  + bz0, 0.0f)
                           + fmaxf(a4[2] + __low2float(c23)  + bz0, 0.0f);
            colsum[nt][1] += fmaxf(a4[1] + __high2float(c01) + bz1, 0.0f)
                           + fmaxf(a4[3] + __high2float(c23) + bz1, 0.0f);
        }
    }
#pragma unroll
    for (int nt = 0; nt < 4; nt++)
#pragma unroll
        for (int j = 0; j < 2; j++)
#pragma unroll
            for (int o = 4; o < 32; o <<= 1)
                colsum[nt][j] += __shfl_xor_sync(0xffffffffu, colsum[nt][j], o);

    __syncthreads();
    float* sred = reinterpret_cast<float*>(smem);   // [4 (wm)][64 cols]
    if (lane < 4) {
#pragma unroll
        for (int nt = 0; nt < 4; nt++) {
            int cl = wn * 32 + nt * 8 + lane * 2;
            sred[wm * 64 + cl]     = colsum[nt][0];
            sred[wm * 64 + cl + 1] = colsum[nt][1];
        }
    }
    __syncthreads();
    if (tid < 64) {
        float s = sred[tid] + sred[64 + tid] + sred[128 + tid] + sred[192 + tid];
        g_h2sum[(size_t)blockIdx.y * H2 + n0 + tid] = s;
    }
}

// ---------------------------------------------------------------------------
// chunk_logits from per-chunk sums: logits[c][e] = (sum[c]/128)·w3[:,e] + b3[e]
__global__ void chunk_logits_small(const float* __restrict__ w3,
                                   const float* __restrict__ b3)
{
    __shared__ float w3s[H2 * EE];
    __shared__ float red[4][EE];
    const int tid = threadIdx.x;  // 128

    for (int i = tid; i < H2 * EE; i += 128) w3s[i] = w3[i];
    __syncthreads();

    const float* srow = g_h2sum + (size_t)blockIdx.x * H2;
    const int k0 = tid * 4;
    float4 hv = *reinterpret_cast<const float4*>(srow + k0);
    float acc[EE];
#pragma unroll
    for (int e = 0; e < EE; e++) {
        acc[e] = hv.x * w3s[(k0 + 0) * EE + e]
               + hv.y * w3s[(k0 + 1) * EE + e]
               + hv.z * w3s[(k0 + 2) * EE + e]
               + hv.w * w3s[(k0 + 3) * EE + e];
    }
    const int lane = tid & 31, warp = tid >> 5;
#pragma unroll
    for (int e = 0; e < EE; e++) {
        float v = acc[e];
#pragma unroll
        for (int o = 16; o > 0; o >>= 1) v += __shfl_down_sync(0xffffffffu, v, o);
        if (lane == 0) red[warp][e] = v;
    }
    __syncthreads();
    if (tid < EE) {
        float s = red[0][tid] + red[1][tid] + red[2][tid] + red[3][tid];
        g_cl[blockIdx.x * EE + tid] = s * (1.0f / 128.0f) + b3[tid];
    }
}

// ---------------------------------------------------------------------------
// finalize (1 block): hysteresis + stats + small outputs; saves sidx
__global__ void finalize_kernel(float* __restrict__ out)
{
    __shared__ float scl[BB * CC * EE];
    __shared__ int   sidx[BB * CC];
    __shared__ int   sflips[BB];
    __shared__ float sent[BB * CC];
    __shared__ float sutil[EE];
    __shared__ float sscal[3];
    const int tid = threadIdx.x;  // 128

    for (int i = tid; i < BB * CC * EE; i += 128) scl[i] = g_cl[i];
    if (tid < EE) sutil[tid] = 0.0f;
    __syncthreads();

    if (tid < BB) {
        int b = tid, prev = 0, flips = 0;
        for (int c = 0; c < CC; c++) {
            const float* l = &scl[(b * CC + c) * EE];
            int top = 0; float best = l[0];
#pragma unroll
            for (int e = 1; e < EE; e++)
                if (l[e] > best) { best = l[e]; top = e; }
            int fin;
            if (c == 0) fin = top;
            else {
                bool sw = (l[top] - l[prev]) > TAU_F;
                flips += sw ? 1 : 0;
                fin = sw ? top : prev;
            }
            sidx[b * CC + c] = fin;
            prev = fin;
        }
        sflips[tid] = flips;
    }
    __syncthreads();

    {
        const float* l = &scl[tid * EE];
        float mx = l[0];
#pragma unroll
        for (int e = 1; e < EE; e++) mx = fmaxf(mx, l[e]);
        float p[EE], se = 0.0f;
#pragma unroll
        for (int e = 0; e < EE; e++) { p[e] = expf(l[e] - mx); se += p[e]; }
        float ent = 0.0f, inv = 1.0f / se;
#pragma unroll
        for (int e = 0; e < EE; e++) {
            float pr = p[e] * inv;
            ent -= pr * logf(pr + 1e-8f);
        }
        sent[tid] = ent;
        atomicAdd(&sutil[sidx[tid]], 1.0f);
    }
    __syncthreads();

    if (tid == 0) {
        float es = 0.0f;
        for (int i = 0; i < BB * CC; i++) es += sent[i];
        sscal[0] = es / (float)(BB * CC);
        int fl = sflips[0] + sflips[1] + sflips[2] + sflips[3];
        sscal[1] = (float)fl / (float)(BB * (CC - 1));
        float nrm = 0.0f;
        for (int e = 0; e < EE; e++) {
            float u = sutil[e] / (float)(BB * CC);
            nrm += u * u;
        }
        sscal[2] = sqrtf(nrm);
    }
    __syncthreads();

    if (tid < BB * CC) { g_sidx[tid] = sidx[tid]; out[131072 + tid] = (float)sidx[tid]; }
    for (int i = tid; i < BB * CC * EE; i += 128) out[131200 + i] = scl[i];
    if (tid == 0) out[132224] = sscal[0];
    if (tid < EE) out[132225 + tid] = sutil[tid] / (float)(BB * CC);
    if (tid == 0) { out[132233] = sscal[1]; out[132234] = sscal[2]; }
}

// Wide routing_weights writer: one token (8 floats) per thread
__global__ void routing_weights_kernel(float* __restrict__ out)
{
    int t = blockIdx.x * blockDim.x + threadIdx.x;   // 0..16383
    int b = t >> 12;
    int c = (t >> 7) & 31;
    int id = g_sidx[b * CC + c];
    float vv[EE];
#pragma unroll
    for (int e = 0; e < EE; e++) vv[e] = (e == id) ? 1.0f : 0.0f;
    float4 v0 = {vv[0], vv[1], vv[2], vv[3]};
    float4 v1 = {vv[4], vv[5], vv[6], vv[7]};
    *reinterpret_cast<float4*>(out + (size_t)t * EE)     = v0;
    *reinterpret_cast<float4*>(out + (size_t)t * EE + 4) = v1;
}

// ---------------------------------------------------------------------------
extern "C" void kernel_launch(void* const* d_in, const int* in_sizes, int n_in,
                              void* d_out, int out_size)
{
    const float* x  = (const float*)d_in[0];
    // d_in[1] = prev_expert_indices — dead in reference (chunk 0 takes argmax)
    const float* w1 = (const float*)d_in[2];
    const float* b1 = (const float*)d_in[3];
    const float* w2 = (const float*)d_in[4];
    const float* b2 = (const float*)d_in[5];
    const float* w3 = (const float*)d_in[6];
    const float* b3 = (const float*)d_in[7];
    float* out = (float*)d_out;

    cudaFuncSetAttribute(gemm1_f32a, cudaFuncAttributeMaxDynamicSharedMemorySize, G1_SMEM);
    cudaFuncSetAttribute(gemm2_chunk, cudaFuncAttributeMaxDynamicSharedMemorySize, G2_SMEM);

    __half *w1hi, *h1hi, *w2hi, *w2lo;
    cudaGetSymbolAddress((void**)&w1hi, g_w1hi);
    cudaGetSymbolAddress((void**)&h1hi, g_h1hi);
    cudaGetSymbolAddress((void**)&w2hi, g_w2hi);
    cudaGetSymbolAddress((void**)&w2lo, g_w2lo);

    // weight conversions
    transpose_hi<<<dim3(HH / 32, DD / 32), dim3(32, 8)>>>(w1, DD, HH, w1hi);
    transpose_split<<<dim3(H2 / 32, HH / 32), dim3(32, 8)>>>(w2, HH, H2, w2hi, w2lo);

    // GEMM1: x fp32 [16384,2048] -> h1 fp16 [16384,1024] (single pass,
    // register-side conversion)
    gemm1_f32a<<<dim3(HH / BN_, MM / BM), 256, G1_SMEM>>>(x, w1hi, b1, h1hi);
    // GEMM2: h1 -> per-chunk column sums of h2 (2-pass, fused epilogue)
    gemm2_chunk<<<dim3(H2 / BN_, MM / BM), 256, G2_SMEM>>>(h1hi, w2hi, w2lo, b2);

    chunk_logits_small<<<BB * CC, 128>>>(w3, b3);
    finalize_kernel<<<1, 128>>>(out);
    routing_weights_kernel<<<MM / 256, 256>>>(out);
}

// round 16
// speedup vs baseline: 1.6832x; 1.1397x over previous
#include <cuda_runtime.h>
#include <cuda_fp16.h>
#include <math.h>
#include <stdint.h>

// ---------------------------------------------------------------------------
// Problem constants
#define BB 4
#define SS_ 4096
#define DD 2048
#define HH 1024
#define H2 512
#define EE 8
#define CC 32
#define MM (BB * SS_)   // 16384
#define TAU_F 0.7f

// ---------------------------------------------------------------------------
// Scratch (device globals; no allocations allowed)
__device__ __half g_xhi[(size_t)MM * DD];
__device__ __half g_w1hi[(size_t)HH * DD];   // transposed [N=1024, K=2048]
__device__ __half g_h1hi[(size_t)MM * HH];
__device__ __half g_w2hi[(size_t)H2 * HH];   // transposed [N=512, K=1024]
__device__ __half g_w2lo[(size_t)H2 * HH];
__device__ float  g_h2sum[(size_t)BB * CC * H2];   // per-chunk column sums of h2
__device__ float  g_cl[BB * CC * EE];
__device__ int    g_sidx[BB * CC];

// ---------------------------------------------------------------------------
__device__ __forceinline__ uint32_t smem_u32(const void* p) {
    uint32_t a;
    asm("{ .reg .u64 t; cvta.to.shared.u64 t, %1; cvt.u32.u64 %0, t; }"
        : "=r"(a) : "l"(p));
    return a;
}
__device__ __forceinline__ void cp16(uint32_t saddr, const void* gaddr) {
    asm volatile("cp.async.cg.shared.global [%0], [%1], 16;" :: "r"(saddr), "l"(gaddr));
}
#define CP_COMMIT() asm volatile("cp.async.commit_group;" ::: "memory")
#define CP_WAIT(n)  asm volatile("cp.async.wait_group %0;" :: "n"(n) : "memory")

__device__ __forceinline__ void ldsm4(uint32_t* r, uint32_t addr) {
    asm volatile("ldmatrix.sync.aligned.m8n8.x4.shared.b16 {%0,%1,%2,%3}, [%4];"
        : "=r"(r[0]), "=r"(r[1]), "=r"(r[2]), "=r"(r[3]) : "r"(addr));
}
// fp32-accumulator HMMA
__device__ __forceinline__ void mma16816(float* d, const uint32_t* a, const uint32_t* b) {
    asm volatile("mma.sync.aligned.m16n8k16.row.col.f32.f16.f16.f32 "
        "{%0,%1,%2,%3}, {%4,%5,%6,%7}, {%8,%9}, {%0,%1,%2,%3};"
        : "+f"(d[0]), "+f"(d[1]), "+f"(d[2]), "+f"(d[3])
        : "r"(a[0]), "r"(a[1]), "r"(a[2]), "r"(a[3]), "r"(b[0]), "r"(b[1]));
}
// fp16-accumulator HMMA (weight-residual correction; terms ~2^-11 of main)
__device__ __forceinline__ void mma16816h(uint32_t* d, const uint32_t* a, const uint32_t* b) {
    asm volatile("mma.sync.aligned.m16n8k16.row.col.f16.f16.f16.f16 "
        "{%0,%1}, {%2,%3,%4,%5}, {%6,%7}, {%0,%1};"
        : "+r"(d[0]), "+r"(d[1])
        : "r"(a[0]), "r"(a[1]), "r"(a[2]), "r"(a[3]), "r"(b[0]), "r"(b[1]));
}

// ---------------------------------------------------------------------------
// fp32 -> fp16 (hi only) for x: token-residual error is iid across the 128
// tokens of a chunk (x zero-mean) and suppressed by the chunk-mean.
__global__ void convert_hi(const float* __restrict__ in, __half* __restrict__ ohi,
                           size_t n4)
{
    size_t i = (size_t)blockIdx.x * blockDim.x + threadIdx.x;
    size_t stride = (size_t)gridDim.x * blockDim.x;
    for (; i < n4; i += stride) {
        float4 v = reinterpret_cast<const float4*>(in)[i];
        reinterpret_cast<__half2*>(ohi)[i * 2] =
            __halves2half2(__float2half_rn(v.x), __float2half_rn(v.y));
        reinterpret_cast<__half2*>(ohi)[i * 2 + 1] =
            __halves2half2(__float2half_rn(v.z), __float2half_rn(v.w));
    }
}

// Transpose hi-only: in [K, N] fp32 -> out [N, K] fp16 (w1).
__global__ void transpose_hi(const float* __restrict__ in, int K, int N,
                             __half* __restrict__ ohi)
{
    __shared__ float t[32][33];
    int nb = blockIdx.x * 32, kb = blockIdx.y * 32;
    int tx = threadIdx.x, ty = threadIdx.y;  // (32, 8)
#pragma unroll
    for (int i = 0; i < 4; i++) {
        int kr = kb + ty + i * 8;
        t[ty + i * 8][tx] = in[(size_t)kr * N + nb + tx];
    }
    __syncthreads();
#pragma unroll
    for (int i = 0; i < 4; i++) {
        int nr = nb + ty + i * 8;
        ohi[(size_t)nr * K + kb + tx] = __float2half_rn(t[tx][ty + i * 8]);
    }
}

// Transposing split (w2 keeps its correction pass: h1 >= 0 post-ReLU, so
// w2-residual error would NOT average out over the chunk).
__global__ void transpose_split(const float* __restrict__ in, int K, int N,
                                __half* __restrict__ ohi, __half* __restrict__ olo)
{
    __shared__ float t[32][33];
    int nb = blockIdx.x * 32, kb = blockIdx.y * 32;
    int tx = threadIdx.x, ty = threadIdx.y;  // (32, 8)
#pragma unroll
    for (int i = 0; i < 4; i++) {
        int kr = kb + ty + i * 8;
        t[ty + i * 8][tx] = in[(size_t)kr * N + nb + tx];
    }
    __syncthreads();
#pragma unroll
    for (int i = 0; i < 4; i++) {
        int nr = nb + ty + i * 8;
        float v = t[tx][ty + i * 8];
        __half h = __float2half_rn(v);
        __half l = __float2half_rn(v - __half2float(h));
        ohi[(size_t)nr * K + kb + tx] = h;
        olo[(size_t)nr * K + kb + tx] = l;
    }
}

// ---------------------------------------------------------------------------
// Common tile geometry
#define BM 128
#define BN_ 64
#define BKH 32          // K halves per stage
#define PITCH 40        // halves per smem row (80 B, conflict-friendly)
#define A16_BYTES (BM * PITCH * 2)      // 10240
#define B_BYTES (BN_ * PITCH * 2)       // 5120 per B array

// ---------------------------------------------------------------------------
// GEMM1 single-pass fp16 HMMA:  h1 = relu(x16·w1hi^T + b1)
// Proven ldmatrix pipeline (the only A-path that reaches the HMMA duty floor).
// ---------------------------------------------------------------------------
#define G1_STAGE (A16_BYTES + B_BYTES)   // 15360
#define G1_SMEM (3 * G1_STAGE)           // 46080 -> 2 CTAs/SM

__global__ __launch_bounds__(256, 2) void gemm1_f16(
    const __half* __restrict__ Ahi, const __half* __restrict__ Bhi,
    const float* __restrict__ bias, __half* __restrict__ Ohi)
{
    extern __shared__ char smem[];
    const uint32_t sb = smem_u32(smem);
    const int K = DD, NC = K / BKH;        // 2048, 64
    const int tid = threadIdx.x, wid = tid >> 5, lane = tid & 31;
    const int m0 = blockIdx.y * BM, n0 = blockIdx.x * BN_;
    const int wm = wid & 3, wn = wid >> 2; // warp grid 4 x 2, tile 32x32

    float acc[2][4][4];
#pragma unroll
    for (int i = 0; i < 2; i++)
#pragma unroll
        for (int j = 0; j < 4; j++)
#pragma unroll
            for (int k = 0; k < 4; k++) acc[i][j][k] = 0.0f;

    auto load_stage = [&](int s, int kc) {
        uint32_t st = sb + s * G1_STAGE;
#pragma unroll
        for (int i = 0; i < 2; i++) {
            int s4 = tid + i * 256;
            int row = s4 >> 2, seg = s4 & 3;
            cp16(st + row * (PITCH * 2) + seg * 16,
                 Ahi + (size_t)(m0 + row) * K + kc + seg * 8);
        }
        {
            int row = tid >> 2, seg = tid & 3;
            cp16(st + A16_BYTES + row * (PITCH * 2) + seg * 16,
                 Bhi + (size_t)(n0 + row) * K + kc + seg * 8);
        }
        CP_COMMIT();
    };

    const int grp = lane >> 3, lr = lane & 7;
    const int a_row = (grp & 1) * 8 + lr;
    const int a_k   = (grp >> 1) * 8;
    const int b_row = (grp >> 1) * 8 + lr;
    const int b_k   = (grp & 1) * 8;

    uint32_t ah[2][4], bh[2][4];

    load_stage(0, 0);
    load_stage(1, BKH);

    for (int c = 0; c < NC; c++) {
        if (c == NC - 1) { CP_WAIT(0); } else { CP_WAIT(1); }
        __syncthreads();
        if (c + 2 < NC) load_stage((c + 2) % 3, (c + 2) * BKH);

        const uint32_t st = sb + (c % 3) * G1_STAGE;
#pragma unroll
        for (int k16 = 0; k16 < 2; k16++) {
            const int koff = k16 * 16;
#pragma unroll
            for (int mt = 0; mt < 2; mt++) {
                uint32_t ao = (uint32_t)((wm * 32 + mt * 16 + a_row) * (PITCH * 2)
                                         + (koff + a_k) * 2);
                ldsm4(ah[mt], st + ao);
            }
#pragma unroll
            for (int np = 0; np < 2; np++) {
                uint32_t bo = (uint32_t)((wn * 32 + np * 16 + b_row) * (PITCH * 2)
                                         + (koff + b_k) * 2);
                ldsm4(bh[np], st + A16_BYTES + bo);
            }
#pragma unroll
            for (int mt = 0; mt < 2; mt++)
#pragma unroll
                for (int nt = 0; nt < 4; nt++)
                    mma16816(acc[mt][nt], ah[mt], &bh[nt >> 1][(nt & 1) * 2]);
        }
    }

    // epilogue: bias + relu, fp16 store
    const int cr = lane >> 2, ccol = (lane & 3) * 2;
#pragma unroll
    for (int mt = 0; mt < 2; mt++) {
#pragma unroll
        for (int nt = 0; nt < 4; nt++) {
            float* a4 = acc[mt][nt];
            int r0 = m0 + wm * 32 + mt * 16 + cr;
            int col = n0 + wn * 32 + nt * 8 + ccol;
            float bz0 = bias[col], bz1 = bias[col + 1];
            float v00 = fmaxf(a4[0] + bz0, 0.0f);
            float v01 = fmaxf(a4[1] + bz1, 0.0f);
            float v10 = fmaxf(a4[2] + bz0, 0.0f);
            float v11 = fmaxf(a4[3] + bz1, 0.0f);
            *reinterpret_cast<__half2*>(Ohi + (size_t)r0 * HH + col) =
                __halves2half2(__float2half_rn(v00), __float2half_rn(v01));
            *reinterpret_cast<__half2*>(Ohi + (size_t)(r0 + 8) * HH + col) =
                __halves2half2(__float2half_rn(v10), __float2half_rn(v11));
        }
    }
}

// ---------------------------------------------------------------------------
// GEMM2: 2-pass (hh fp32 + hl fp16 correction), fused per-chunk column-sum
// epilogue -> g_h2sum. Each CTA = one 128-token chunk x 64 cols.
// ---------------------------------------------------------------------------
#define SB_STAGE (A16_BYTES + 2 * B_BYTES)   // 20480
#define G2_SMEM (3 * SB_STAGE)               // 61440 -> 2 CTAs/SM

__global__ __launch_bounds__(256, 2) void gemm2_chunk(
    const __half* __restrict__ Ahi,
    const __half* __restrict__ Bhi, const __half* __restrict__ Blo,
    const float* __restrict__ bias)
{
    extern __shared__ char smem[];
    const uint32_t sb = smem_u32(smem);
    const int K = HH, NC = K / BKH;        // 1024, 32
    const int tid = threadIdx.x, wid = tid >> 5, lane = tid & 31;
    const int m0 = blockIdx.y * BM, n0 = blockIdx.x * BN_;
    const int wm = wid & 3, wn = wid >> 2;

    float acc[2][4][4];
    uint32_t cacc[2][4][2];
#pragma unroll
    for (int i = 0; i < 2; i++)
#pragma unroll
        for (int j = 0; j < 4; j++) {
#pragma unroll
            for (int k = 0; k < 4; k++) acc[i][j][k] = 0.0f;
            cacc[i][j][0] = 0u; cacc[i][j][1] = 0u;
        }

    auto load_stage = [&](int s, int kc) {
        uint32_t st = sb + s * SB_STAGE;
#pragma unroll
        for (int i = 0; i < 2; i++) {
            int s4 = tid + i * 256;
            int row = s4 >> 2, seg = s4 & 3;
            cp16(st + row * (PITCH * 2) + seg * 16,
                 Ahi + (size_t)(m0 + row) * K + kc + seg * 8);
        }
        {
            int row = tid >> 2, seg = tid & 3;
            uint32_t o = row * (PITCH * 2) + seg * 16;
            size_t gb = (size_t)(n0 + row) * K + kc + seg * 8;
            cp16(st + A16_BYTES + o,           Bhi + gb);
            cp16(st + A16_BYTES + B_BYTES + o, Blo + gb);
        }
        CP_COMMIT();
    };

    const int grp = lane >> 3, lr = lane & 7;
    const int a_row = (grp & 1) * 8 + lr;
    const int a_k   = (grp >> 1) * 8;
    const int b_row = (grp >> 1) * 8 + lr;
    const int b_k   = (grp & 1) * 8;

    uint32_t ah[2][4], bh[2][4], bl[2][4];

    load_stage(0, 0);
    load_stage(1, BKH);

    for (int c = 0; c < NC; c++) {
        if (c == NC - 1) { CP_WAIT(0); } else { CP_WAIT(1); }
        __syncthreads();
        if (c + 2 < NC) load_stage((c + 2) % 3, (c + 2) * BKH);

        const uint32_t st = sb + (c % 3) * SB_STAGE;
#pragma unroll
        for (int k16 = 0; k16 < 2; k16++) {
            const int koff = k16 * 16;
#pragma unroll
            for (int mt = 0; mt < 2; mt++) {
                uint32_t ao = (uint32_t)((wm * 32 + mt * 16 + a_row) * (PITCH * 2)
                                         + (koff + a_k) * 2);
                ldsm4(ah[mt], st + ao);
            }
#pragma unroll
            for (int np = 0; np < 2; np++) {
                uint32_t bo = (uint32_t)((wn * 32 + np * 16 + b_row) * (PITCH * 2)
                                         + (koff + b_k) * 2);
                ldsm4(bh[np], st + A16_BYTES + bo);
                ldsm4(bl[np], st + A16_BYTES + B_BYTES + bo);
            }
#pragma unroll
            for (int mt = 0; mt < 2; mt++)
#pragma unroll
                for (int nt = 0; nt < 4; nt++)
                    mma16816(acc[mt][nt], ah[mt], &bh[nt >> 1][(nt & 1) * 2]);
#pragma unroll
            for (int mt = 0; mt < 2; mt++)
#pragma unroll
                for (int nt = 0; nt < 4; nt++)
                    mma16816h(cacc[mt][nt], ah[mt], &bl[nt >> 1][(nt & 1) * 2]);
        }
    }

    // epilogue: bias+relu, then per-chunk column sums over the 128 rows
    const int ccol = (lane & 3) * 2;
    float colsum[4][2];
#pragma unroll
    for (int nt = 0; nt < 4; nt++) { colsum[nt][0] = 0.0f; colsum[nt][1] = 0.0f; }
#pragma unroll
    for (int mt = 0; mt < 2; mt++) {
#pragma unroll
        for (int nt = 0; nt < 4; nt++) {
            float* a4 = acc[mt][nt];
            __half2 c01 = *reinterpret_cast<__half2*>(&cacc[mt][nt][0]);
            __half2 c23 = *reinterpret_cast<__half2*>(&cacc[mt][nt][1]);
            int col = n0 + wn * 32 + nt * 8 + ccol;
            float bz0 = bias[col], bz1 = bias[col + 1];
            colsum[nt][0] += fmaxf(a4[0] + __low2float(c01)  + bz0, 0.0f)
                           + fmaxf(a4[2] + __low2float(c23)  + bz0, 0.0f);
            colsum[nt][1] += fmaxf(a4[1] + __high2float(c01) + bz1, 0.0f)
                           + fmaxf(a4[3] + __high2float(c23) + bz1, 0.0f);
        }
    }
#pragma unroll
    for (int nt = 0; nt < 4; nt++)
#pragma unroll
        for (int j = 0; j < 2; j++)
#pragma unroll
            for (int o = 4; o < 32; o <<= 1)
                colsum[nt][j] += __shfl_xor_sync(0xffffffffu, colsum[nt][j], o);

    __syncthreads();
    float* sred = reinterpret_cast<float*>(smem);   // [4 (wm)][64 cols]
    if (lane < 4) {
#pragma unroll
        for (int nt = 0; nt < 4; nt++) {
            int cl = wn * 32 + nt * 8 + lane * 2;
            sred[wm * 64 + cl]     = colsum[nt][0];
            sred[wm * 64 + cl + 1] = colsum[nt][1];
        }
    }
    __syncthreads();
    if (tid < 64) {
        float s = sred[tid] + sred[64 + tid] + sred[128 + tid] + sred[192 + tid];
        g_h2sum[(size_t)blockIdx.y * H2 + n0 + tid] = s;
    }
}

// ---------------------------------------------------------------------------
// chunk_logits from per-chunk sums: logits[c][e] = (sum[c]/128)·w3[:,e] + b3[e]
__global__ void chunk_logits_small(const float* __restrict__ w3,
                                   const float* __restrict__ b3)
{
    __shared__ float w3s[H2 * EE];
    __shared__ float red[4][EE];
    const int tid = threadIdx.x;  // 128

    for (int i = tid; i < H2 * EE; i += 128) w3s[i] = w3[i];
    __syncthreads();

    const float* srow = g_h2sum + (size_t)blockIdx.x * H2;
    const int k0 = tid * 4;
    float4 hv = *reinterpret_cast<const float4*>(srow + k0);
    float acc[EE];
#pragma unroll
    for (int e = 0; e < EE; e++) {
        acc[e] = hv.x * w3s[(k0 + 0) * EE + e]
               + hv.y * w3s[(k0 + 1) * EE + e]
               + hv.z * w3s[(k0 + 2) * EE + e]
               + hv.w * w3s[(k0 + 3) * EE + e];
    }
    const int lane = tid & 31, warp = tid >> 5;
#pragma unroll
    for (int e = 0; e < EE; e++) {
        float v = acc[e];
#pragma unroll
        for (int o = 16; o > 0; o >>= 1) v += __shfl_down_sync(0xffffffffu, v, o);
        if (lane == 0) red[warp][e] = v;
    }
    __syncthreads();
    if (tid < EE) {
        float s = red[0][tid] + red[1][tid] + red[2][tid] + red[3][tid];
        g_cl[blockIdx.x * EE + tid] = s * (1.0f / 128.0f) + b3[tid];
    }
}

// ---------------------------------------------------------------------------
// finalize (1 block): hysteresis + stats + small outputs; saves sidx
__global__ void finalize_kernel(float* __restrict__ out)
{
    __shared__ float scl[BB * CC * EE];
    __shared__ int   sidx[BB * CC];
    __shared__ int   sflips[BB];
    __shared__ float sent[BB * CC];
    __shared__ float sutil[EE];
    __shared__ float sscal[3];
    const int tid = threadIdx.x;  // 128

    for (int i = tid; i < BB * CC * EE; i += 128) scl[i] = g_cl[i];
    if (tid < EE) sutil[tid] = 0.0f;
    __syncthreads();

    if (tid < BB) {
        int b = tid, prev = 0, flips = 0;
        for (int c = 0; c < CC; c++) {
            const float* l = &scl[(b * CC + c) * EE];
            int top = 0; float best = l[0];
#pragma unroll
            for (int e = 1; e < EE; e++)
                if (l[e] > best) { best = l[e]; top = e; }
            int fin;
            if (c == 0) fin = top;
            else {
                bool sw = (l[top] - l[prev]) > TAU_F;
                flips += sw ? 1 : 0;
                fin = sw ? top : prev;
            }
            sidx[b * CC + c] = fin;
            prev = fin;
        }
        sflips[tid] = flips;
    }
    __syncthreads();

    {
        const float* l = &scl[tid * EE];
        float mx = l[0];
#pragma unroll
        for (int e = 1; e < EE; e++) mx = fmaxf(mx, l[e]);
        float p[EE], se = 0.0f;
#pragma unroll
        for (int e = 0; e < EE; e++) { p[e] = expf(l[e] - mx); se += p[e]; }
        float ent = 0.0f, inv = 1.0f / se;
#pragma unroll
        for (int e = 0; e < EE; e++) {
            float pr = p[e] * inv;
            ent -= pr * logf(pr + 1e-8f);
        }
        sent[tid] = ent;
        atomicAdd(&sutil[sidx[tid]], 1.0f);
    }
    __syncthreads();

    if (tid == 0) {
        float es = 0.0f;
        for (int i = 0; i < BB * CC; i++) es += sent[i];
        sscal[0] = es / (float)(BB * CC);
        int fl = sflips[0] + sflips[1] + sflips[2] + sflips[3];
        sscal[1] = (float)fl / (float)(BB * (CC - 1));
        float nrm = 0.0f;
        for (int e = 0; e < EE; e++) {
            float u = sutil[e] / (float)(BB * CC);
            nrm += u * u;
        }
        sscal[2] = sqrtf(nrm);
    }
    __syncthreads();

    if (tid < BB * CC) { g_sidx[tid] = sidx[tid]; out[131072 + tid] = (float)sidx[tid]; }
    for (int i = tid; i < BB * CC * EE; i += 128) out[131200 + i] = scl[i];
    if (tid == 0) out[132224] = sscal[0];
    if (tid < EE) out[132225 + tid] = sutil[tid] / (float)(BB * CC);
    if (tid == 0) { out[132233] = sscal[1]; out[132234] = sscal[2]; }
}

// Wide routing_weights writer: one token (8 floats) per thread
__global__ void routing_weights_kernel(float* __restrict__ out)
{
    int t = blockIdx.x * blockDim.x + threadIdx.x;   // 0..16383
    int b = t >> 12;
    int c = (t >> 7) & 31;
    int id = g_sidx[b * CC + c];
    float vv[EE];
#pragma unroll
    for (int e = 0; e < EE; e++) vv[e] = (e == id) ? 1.0f : 0.0f;
    float4 v0 = {vv[0], vv[1], vv[2], vv[3]};
    float4 v1 = {vv[4], vv[5], vv[6], vv[7]};
    *reinterpret_cast<float4*>(out + (size_t)t * EE)     = v0;
    *reinterpret_cast<float4*>(out + (size_t)t * EE + 4) = v1;
}

// ---------------------------------------------------------------------------
extern "C" void kernel_launch(void* const* d_in, const int* in_sizes, int n_in,
                              void* d_out, int out_size)
{
    const float* x  = (const float*)d_in[0];
    // d_in[1] = prev_expert_indices — dead in reference (chunk 0 takes argmax)
    const float* w1 = (const float*)d_in[2];
    const float* b1 = (const float*)d_in[3];
    const float* w2 = (const float*)d_in[4];
    const float* b2 = (const float*)d_in[5];
    const float* w3 = (const float*)d_in[6];
    const float* b3 = (const float*)d_in[7];
    float* out = (float*)d_out;

    cudaFuncSetAttribute(gemm1_f16,  cudaFuncAttributeMaxDynamicSharedMemorySize, G1_SMEM);
    cudaFuncSetAttribute(gemm2_chunk, cudaFuncAttributeMaxDynamicSharedMemorySize, G2_SMEM);

    __half *xhi, *w1hi, *h1hi, *w2hi, *w2lo;
    cudaGetSymbolAddress((void**)&xhi, g_xhi);
    cudaGetSymbolAddress((void**)&w1hi, g_w1hi);
    cudaGetSymbolAddress((void**)&h1hi, g_h1hi);
    cudaGetSymbolAddress((void**)&w2hi, g_w2hi);
    cudaGetSymbolAddress((void**)&w2lo, g_w2lo);

    // conversions
    convert_hi<<<2048, 256>>>(x, xhi, (size_t)MM * DD / 4);
    transpose_hi<<<dim3(HH / 32, DD / 32), dim3(32, 8)>>>(w1, DD, HH, w1hi);
    transpose_split<<<dim3(H2 / 32, HH / 32), dim3(32, 8)>>>(w2, HH, H2, w2hi, w2lo);

    // GEMM1: x16 [16384,2048] -> h1 fp16 [16384,1024] (single pass, ldmatrix)
    gemm1_f16<<<dim3(HH / BN_, MM / BM), 256, G1_SMEM>>>(xhi, w1hi, b1, h1hi);
    // GEMM2: h1 -> per-chunk column sums of h2 (2-pass, fused epilogue)
    gemm2_chunk<<<dim3(H2 / BN_, MM / BM), 256, G2_SMEM>>>(h1hi, w2hi, w2lo, b2);

    chunk_logits_small<<<BB * CC, 128>>>(w3, b3);
    finalize_kernel<<<1, 128>>>(out);
    routing_weights_kernel<<<MM / 256, 256>>>(out);
}